// round 11
// baseline (speedup 1.0000x reference)
#include <cuda_runtime.h>
#include <cuda_fp16.h>
#include <cstdint>

// ---------------- problem constants ----------------
#define Bv   2
#define Hv   16
#define Sv   2048
#define Dv   64
#define TQ   128           // query rows per CTA (4 warps x 32 rows)
#define TK   64            // keys per tile
#define NT   (Sv / TK)     // 32 tiles
#define NTH  128
#define KVN  (Bv*Hv*Sv*Dv) // 4,194,304 elements per tensor

// fp16 scratch for K and V (converted once by prepass kernel)
__device__ __align__(16) uint4 g_kh[KVN / 8];   // 8 MB
__device__ __align__(16) uint4 g_vh[KVN / 8];   // 8 MB

// ---------------- smem layout (bytes), 2-stage ----------------
#define OFF_K(s)  ((uint32_t)(s)*8192u)
#define OFF_V(s)  (16384u + (uint32_t)(s)*8192u)
#define OFF_M(s)  (32768u + (uint32_t)(s)*32768u)
#define SMEM_TOT  98304

// ---------------- helpers ----------------
__device__ __forceinline__ uint32_t smem_u32(const void* p) {
    uint32_t a;
    asm("{ .reg .u64 t; cvta.to.shared.u64 t, %1; cvt.u32.u64 %0, t; }" : "=r"(a) : "l"(p));
    return a;
}
__device__ __forceinline__ uint32_t f2h2(float x, float y) {
    __half2 h = __floats2half2_rn(x, y);
    return *reinterpret_cast<uint32_t*>(&h);
}
__device__ __forceinline__ void ldsm2(uint32_t& r0, uint32_t& r1, uint32_t a) {
    asm volatile("ldmatrix.sync.aligned.m8n8.x2.shared.b16 {%0,%1}, [%2];"
                 : "=r"(r0), "=r"(r1) : "r"(a));
}
__device__ __forceinline__ void ldsm2t(uint32_t& r0, uint32_t& r1, uint32_t a) {
    asm volatile("ldmatrix.sync.aligned.m8n8.x2.trans.shared.b16 {%0,%1}, [%2];"
                 : "=r"(r0), "=r"(r1) : "r"(a));
}
__device__ __forceinline__ void mma16816(float* c, const uint32_t* a, uint32_t b0, uint32_t b1) {
    asm volatile(
        "mma.sync.aligned.m16n8k16.row.col.f32.f16.f16.f32 "
        "{%0,%1,%2,%3}, {%4,%5,%6,%7}, {%8,%9}, {%0,%1,%2,%3};"
        : "+f"(c[0]), "+f"(c[1]), "+f"(c[2]), "+f"(c[3])
        : "r"(a[0]), "r"(a[1]), "r"(a[2]), "r"(a[3]), "r"(b0), "r"(b1));
}
// SW128 swizzle for a [64 rows][128B] fp16 tile
__device__ __forceinline__ uint32_t swz(int row, int cb) {
    return (uint32_t)(row * 128 + (cb ^ ((row & 7) << 4)));
}
__device__ __forceinline__ void cpasync16(uint32_t dst, const void* src) {
    asm volatile("cp.async.cg.shared.global [%0], [%1], 16;"
                 :: "r"(dst), "l"(src) : "memory");
}
__device__ __forceinline__ float2 lds64(uint32_t a) {
    float2 v;
    asm volatile("ld.shared.v2.f32 {%0,%1}, [%2];" : "=f"(v.x), "=f"(v.y) : "r"(a));
    return v;
}
#define CP_COMMIT()  asm volatile("cp.async.commit_group;" ::: "memory")
#define CP_WAIT1()   asm volatile("cp.async.wait_group 1;" ::: "memory")

// ---------------- prepass: fp32 K/V -> fp16 scratch ----------------
__global__ __launch_bounds__(256)
void convert_kv_kernel(const float* __restrict__ k, const float* __restrict__ v)
{
    int i = blockIdx.x * blockDim.x + threadIdx.x;
    const float4* k4 = (const float4*)k;
    const float4* v4 = (const float4*)v;
    float4 a0 = k4[2 * i], a1 = k4[2 * i + 1];
    float4 b0 = v4[2 * i], b1 = v4[2 * i + 1];
    uint4 ko, vo;
    ko.x = f2h2(a0.x, a0.y); ko.y = f2h2(a0.z, a0.w);
    ko.z = f2h2(a1.x, a1.y); ko.w = f2h2(a1.z, a1.w);
    vo.x = f2h2(b0.x, b0.y); vo.y = f2h2(b0.z, b0.w);
    vo.z = f2h2(b1.x, b1.y); vo.w = f2h2(b1.z, b1.w);
    g_kh[i] = ko;
    g_vh[i] = vo;
}

// ---------------- main kernel: 4 warps x 32 rows ----------------
__global__ __launch_bounds__(NTH, 2)
void flashret_fp16_kernel(const float* __restrict__ q,
                          const float* __restrict__ mask,
                          float* __restrict__ out)
{
    extern __shared__ __align__(1024) uint8_t smem[];
    const uint32_t sb = smem_u32(smem);

    const int tid  = threadIdx.x;
    const int warp = tid >> 5;          // 0..3
    const int lane = tid & 31;
    const int tq   = lane >> 2;
    const int qd   = lane & 3;
    const int R    = warp * 32;         // warp owns rows R..R+31

    const int bh = blockIdx.y;
    const int qt = blockIdx.x;

    const size_t rowb = (size_t)bh * Sv + (size_t)qt * TQ + R + tq;
    const float* qb = q + rowb * Dv;          // row (R+tq); +8/+16/+24 via offsets
    float*       ob = out + rowb * Dv;
    const __half* khb = (const __half*)g_kh + (size_t)bh * Sv * Dv;
    const __half* vhb = (const __half*)g_vh + (size_t)bh * Sv * Dv;

    // KV producer mapping: rows n0+16i (i=0..3), 16B chunk c0
    const int n0 = tid >> 3, c0 = tid & 7;
    const uint32_t sob = swz(n0, c0 * 16);    // +2048*i for rows n0+16i

    // Mask producer mapping: rows mrow0+8i (i=0..15), 16B chunk mm
    const int mrow0 = tid >> 4;               // 0..7
    const int mm    = tid & 15;
    const uint32_t mswz = (uint32_t)((mm ^ (2 * (mrow0 & 7))) * 16);
    const float* mCTA  = mask + ((size_t)bh * Sv + (size_t)qt * TQ) * (size_t)Sv;
    const float* msrc0 = mCTA + (size_t)mrow0 * Sv + mm * 4;
    const uint32_t mdst0 = (uint32_t)(mrow0 * 256) + mswz;

    // ---- Q A-fragments (M=32: two 16-row frags per kb) ----
    uint32_t qa[4][8];   // [kb][m*4 + i]
    #pragma unroll
    for (int kb = 0; kb < 4; ++kb) {
        #pragma unroll
        for (int m = 0; m < 2; ++m) {
            float2 a0 = *(const float2*)(qb + (16 * m)     * Dv + kb * 16 + 2 * qd);
            float2 a1 = *(const float2*)(qb + (16 * m + 8) * Dv + kb * 16 + 2 * qd);
            float2 a2 = *(const float2*)(qb + (16 * m)     * Dv + kb * 16 + 8 + 2 * qd);
            float2 a3 = *(const float2*)(qb + (16 * m + 8) * Dv + kb * 16 + 8 + 2 * qd);
            qa[kb][m*4+0] = f2h2(a0.x, a0.y);
            qa[kb][m*4+1] = f2h2(a1.x, a1.y);
            qa[kb][m*4+2] = f2h2(a2.x, a2.y);
            qa[kb][m*4+3] = f2h2(a3.x, a3.y);
        }
    }

    float o[8][8];       // [j][m*4+i] : 32 rows x 64 cols
    #pragma unroll
    for (int j = 0; j < 8; ++j)
        #pragma unroll
        for (int i = 0; i < 8; ++i) o[j][i] = 0.0f;
    float r00 = 0.0f, r01 = 0.0f, r10 = 0.0f, r11 = 0.0f;

    // ---- async issue helpers ----
    auto issue_kv = [&](int kt) {
        const uint32_t KB = sb + OFF_K(kt & 1);
        const uint32_t VB = sb + OFF_V(kt & 1);
        const __half* ks = khb + ((size_t)kt * TK + n0) * Dv + c0 * 8;
        const __half* vs = vhb + ((size_t)kt * TK + n0) * Dv + c0 * 8;
        #pragma unroll
        for (int i = 0; i < 4; ++i) {
            cpasync16(KB + sob + 2048u * i, ks + (size_t)(16 * i) * Dv);
            cpasync16(VB + sob + 2048u * i, vs + (size_t)(16 * i) * Dv);
        }
    };
    auto issue_mask = [&](int kt) {
        const uint32_t MB = sb + OFF_M(kt & 1) + mdst0;
        const float* ms = msrc0 + (size_t)kt * TK;
        #pragma unroll
        for (int i = 0; i < 16; ++i)
            cpasync16(MB + (uint32_t)(i * 8 * 256), ms + (size_t)i * 8 * Sv);
    };

    issue_kv(0);
    issue_mask(0);
    CP_COMMIT();

    const int lrow8  = lane & 7;
    const int lkhalf = ((lane >> 3) & 1) * 16;
    const int lrow16 = lane & 15;

    for (int kt = 0; kt < NT; ++kt) {
        __syncthreads();                 // WAR: prior reads of reissued slot done
        if (kt + 1 < NT) { issue_kv(kt + 1); issue_mask(kt + 1); }
        CP_COMMIT();
        CP_WAIT1();                      // tile kt complete
        __syncthreads();                 // visibility

        const uint32_t KBc = sb + OFF_K(kt & 1);
        const uint32_t VBc = sb + OFF_V(kt & 1);
        const uint32_t mb0 = sb + OFF_M(kt & 1) + (uint32_t)((R + tq) * 256) + (uint32_t)(qd * 8);
        const uint32_t mb1 = mb0 + 16 * 256;

        // ---- two key-halves of 32 keys each ----
        #pragma unroll
        for (int h = 0; h < 2; ++h) {
            const int krow = 32 * h;

            // GEMM1 half: S(32 x 32) = Q @ K_half^T
            float c[2][4][4];
            #pragma unroll
            for (int m = 0; m < 2; ++m)
                #pragma unroll
                for (int jj = 0; jj < 4; ++jj)
                    c[m][jj][0] = c[m][jj][1] = c[m][jj][2] = c[m][jj][3] = 0.0f;
            #pragma unroll
            for (int jj = 0; jj < 4; ++jj) {
                #pragma unroll
                for (int kb = 0; kb < 4; ++kb) {
                    uint32_t b0, b1;
                    ldsm2(b0, b1, KBc + swz(krow + 8 * jj + lrow8, kb * 32 + lkhalf));
                    mma16816(c[0][jj], qa[kb] + 0, b0, b1);
                    mma16816(c[1][jj], qa[kb] + 4, b0, b1);
                }
            }

            // mask multiply + |.| + pack P A-frags
            uint32_t pa[2][8];   // [kb'][m*4+i]
            #pragma unroll
            for (int jj = 0; jj < 4; ++jj) {
                const int jg = 4 * h + jj;
                const uint32_t off = (uint32_t)((jg ^ tq) << 5);
                float2 am0 = lds64(mb0 + off);
                float2 bm0 = lds64(mb0 + off + 2048);
                float2 am1 = lds64(mb1 + off);
                float2 bm1 = lds64(mb1 + off + 2048);
                float p00 = c[0][jj][0] * am0.x;
                float p01 = c[0][jj][1] * am0.y;
                float p02 = c[0][jj][2] * bm0.x;
                float p03 = c[0][jj][3] * bm0.y;
                float p10 = c[1][jj][0] * am1.x;
                float p11 = c[1][jj][1] * am1.y;
                float p12 = c[1][jj][2] * bm1.x;
                float p13 = c[1][jj][3] * bm1.y;
                r00 += fabsf(p00) + fabsf(p01);
                r01 += fabsf(p02) + fabsf(p03);
                r10 += fabsf(p10) + fabsf(p11);
                r11 += fabsf(p12) + fabsf(p13);
                const int kb2 = jj >> 1, hh = (jj & 1) << 1;
                pa[kb2][hh]     = f2h2(p00, p01);
                pa[kb2][hh + 1] = f2h2(p02, p03);
                pa[kb2][4 + hh]     = f2h2(p10, p11);
                pa[kb2][4 + hh + 1] = f2h2(p12, p13);
            }

            // GEMM2 half: O(32 x 64) += P_half @ V_half
            #pragma unroll
            for (int j = 0; j < 8; ++j) {
                #pragma unroll
                for (int kb2 = 0; kb2 < 2; ++kb2) {
                    uint32_t b0, b1;
                    ldsm2t(b0, b1, VBc + swz(krow + kb2 * 16 + lrow16, j * 16));
                    mma16816(o[j] + 0, pa[kb2] + 0, b0, b1);
                    mma16816(o[j] + 4, pa[kb2] + 4, b0, b1);
                }
            }
        }
    }

    // ---- normalizer quad-reductions ----
    r00 += __shfl_xor_sync(0xffffffffu, r00, 1);
    r00 += __shfl_xor_sync(0xffffffffu, r00, 2);
    r01 += __shfl_xor_sync(0xffffffffu, r01, 1);
    r01 += __shfl_xor_sync(0xffffffffu, r01, 2);
    r10 += __shfl_xor_sync(0xffffffffu, r10, 1);
    r10 += __shfl_xor_sync(0xffffffffu, r10, 2);
    r11 += __shfl_xor_sync(0xffffffffu, r11, 1);
    r11 += __shfl_xor_sync(0xffffffffu, r11, 2);
    const float i00 = 1.0f / fmaxf(r00, 1.0f);
    const float i01 = 1.0f / fmaxf(r01, 1.0f);
    const float i10 = 1.0f / fmaxf(r10, 1.0f);
    const float i11 = 1.0f / fmaxf(r11, 1.0f);

    // ---- epilogue: 4 rows per lane ----
    #pragma unroll
    for (int j = 0; j < 8; ++j) {
        float2 t;
        t.x = o[j][0] * i00;  t.y = o[j][1] * i00;
        *(float2*)(ob + 0 * Dv + 8 * j + 2 * qd) = t;
        t.x = o[j][2] * i01;  t.y = o[j][3] * i01;
        *(float2*)(ob + 8 * Dv + 8 * j + 2 * qd) = t;
        t.x = o[j][4] * i10;  t.y = o[j][5] * i10;
        *(float2*)(ob + 16 * Dv + 8 * j + 2 * qd) = t;
        t.x = o[j][6] * i11;  t.y = o[j][7] * i11;
        *(float2*)(ob + 24 * Dv + 8 * j + 2 * qd) = t;
    }
}

extern "C" void kernel_launch(void* const* d_in, const int* in_sizes, int n_in,
                              void* d_out, int out_size)
{
    const float* q    = (const float*)d_in[0];
    const float* k    = (const float*)d_in[1];
    const float* v    = (const float*)d_in[2];
    const float* mask = (const float*)d_in[3];
    float* out        = (float*)d_out;

    convert_kv_kernel<<<KVN / 8 / 256, 256>>>(k, v);

    cudaFuncSetAttribute(flashret_fp16_kernel,
                         cudaFuncAttributeMaxDynamicSharedMemorySize, SMEM_TOT);
    dim3 grid(Sv / TQ, Bv * Hv);   // (16, 32) = 512 CTAs of 128 threads
    flashret_fp16_kernel<<<grid, NTH, SMEM_TOT>>>(q, mask, out);
}

// round 13
// speedup vs baseline: 1.3467x; 1.3467x over previous
#include <cuda_runtime.h>
#include <cuda_fp16.h>
#include <cstdint>

// ---------------- problem constants ----------------
#define Bv   2
#define Hv   16
#define Sv   2048
#define Dv   64
#define TQ   128           // query rows per CTA (8 warps x 16 rows)
#define TK   64            // keys per tile
#define NT   (Sv / TK)     // 32 tiles
#define NTH  256
#define KVN  (Bv*Hv*Sv*Dv) // 4,194,304 elements per tensor

// fp16 scratch for K and V (converted once by prepass kernel)
__device__ __align__(16) uint4 g_kh[KVN / 8];   // 8 MB
__device__ __align__(16) uint4 g_vh[KVN / 8];   // 8 MB

// ---------------- smem layout (bytes), 2-stage everything ----------------
//  K slot s:  s*8192        (64 rows x 128B, SW128)
//  V slot s:  16384+s*8192
//  M slot s:  32768+s*32768 (128 rows x 256B, XOR-8B swizzled)
#define OFF_K(s)  ((uint32_t)(s)*8192u)
#define OFF_V(s)  (16384u + (uint32_t)(s)*8192u)
#define OFF_M(s)  (32768u + (uint32_t)(s)*32768u)
#define SMEM_TOT  98304

// ---------------- helpers ----------------
__device__ __forceinline__ uint32_t smem_u32(const void* p) {
    uint32_t a;
    asm("{ .reg .u64 t; cvta.to.shared.u64 t, %1; cvt.u32.u64 %0, t; }" : "=r"(a) : "l"(p));
    return a;
}
__device__ __forceinline__ uint32_t f2h2(float x, float y) {
    __half2 h = __floats2half2_rn(x, y);
    return *reinterpret_cast<uint32_t*>(&h);
}
__device__ __forceinline__ void ldsm4(uint32_t& r0, uint32_t& r1, uint32_t& r2, uint32_t& r3, uint32_t a) {
    asm volatile("ldmatrix.sync.aligned.m8n8.x4.shared.b16 {%0,%1,%2,%3}, [%4];"
                 : "=r"(r0), "=r"(r1), "=r"(r2), "=r"(r3) : "r"(a));
}
__device__ __forceinline__ void ldsm4t(uint32_t& r0, uint32_t& r1, uint32_t& r2, uint32_t& r3, uint32_t a) {
    asm volatile("ldmatrix.sync.aligned.m8n8.x4.trans.shared.b16 {%0,%1,%2,%3}, [%4];"
                 : "=r"(r0), "=r"(r1), "=r"(r2), "=r"(r3) : "r"(a));
}
__device__ __forceinline__ void mma16816(float* c, const uint32_t* a, uint32_t b0, uint32_t b1) {
    asm volatile(
        "mma.sync.aligned.m16n8k16.row.col.f32.f16.f16.f32 "
        "{%0,%1,%2,%3}, {%4,%5,%6,%7}, {%8,%9}, {%0,%1,%2,%3};"
        : "+f"(c[0]), "+f"(c[1]), "+f"(c[2]), "+f"(c[3])
        : "r"(a[0]), "r"(a[1]), "r"(a[2]), "r"(a[3]), "r"(b0), "r"(b1));
}
// SW128 swizzle for a [64 rows][128B] fp16 tile
__device__ __forceinline__ uint32_t swz(int row, int cb) {
    return (uint32_t)(row * 128 + (cb ^ ((row & 7) << 4)));
}
__device__ __forceinline__ void cpasync16(uint32_t dst, const void* src) {
    asm volatile("cp.async.cg.shared.global [%0], [%1], 16;"
                 :: "r"(dst), "l"(src) : "memory");
}
__device__ __forceinline__ float2 lds64(uint32_t a) {
    float2 v;
    asm volatile("ld.shared.v2.f32 {%0,%1}, [%2];" : "=f"(v.x), "=f"(v.y) : "r"(a));
    return v;
}
#define CP_COMMIT()  asm volatile("cp.async.commit_group;" ::: "memory")
#define CP_WAIT1()   asm volatile("cp.async.wait_group 1;" ::: "memory")

// ---------------- prepass: fp32 K/V -> fp16 scratch ----------------
__global__ __launch_bounds__(256)
void convert_kv_kernel(const float* __restrict__ k, const float* __restrict__ v)
{
    int i = blockIdx.x * blockDim.x + threadIdx.x;
    const float4* k4 = (const float4*)k;
    const float4* v4 = (const float4*)v;
    float4 a0 = k4[2 * i], a1 = k4[2 * i + 1];
    float4 b0 = v4[2 * i], b1 = v4[2 * i + 1];
    uint4 ko, vo;
    ko.x = f2h2(a0.x, a0.y); ko.y = f2h2(a0.z, a0.w);
    ko.z = f2h2(a1.x, a1.y); ko.w = f2h2(a1.z, a1.w);
    vo.x = f2h2(b0.x, b0.y); vo.y = f2h2(b0.z, b0.w);
    vo.z = f2h2(b1.x, b1.y); vo.w = f2h2(b1.z, b1.w);
    g_kh[i] = ko;
    g_vh[i] = vo;
}

// ---------------- main kernel: 8 warps x 16 rows ----------------
__global__ __launch_bounds__(NTH, 2)
void flashret_fp16_kernel(const float* __restrict__ q,
                          const float* __restrict__ mask,
                          float* __restrict__ out)
{
    extern __shared__ __align__(1024) uint8_t smem[];
    const uint32_t sb = smem_u32(smem);

    const int tid  = threadIdx.x;
    const int warp = tid >> 5;
    const int lane = tid & 31;
    const int tq   = lane >> 2;
    const int qd   = lane & 3;
    const int R    = warp * 16;

    const int bh = blockIdx.y;
    const int qt = blockIdx.x;

    const size_t qrow = (size_t)bh * Sv + (size_t)qt * TQ + R + tq;
    const float* qlo = q + qrow * Dv;
    const float* qhi = qlo + 8 * Dv;
    float* olo = out + qrow * Dv;
    float* ohi = olo + 8 * Dv;
    const __half* khb = (const __half*)g_kh + (size_t)bh * Sv * Dv;
    const __half* vhb = (const __half*)g_vh + (size_t)bh * Sv * Dv;

    // KV producer mapping: rows n0, n0+32; 16B chunk c0 within 128B row
    const int n0 = tid >> 3, c0 = tid & 7;
    const uint32_t so0 = swz(n0, c0 * 16);
    const uint32_t so1 = swz(n0 + 32, c0 * 16);

    // Mask producer mapping: thread covers rows mrow0+16i (i=0..7), 16B chunk mm
    const int mrow0 = tid >> 4;              // 0..15
    const int mm    = tid & 15;              // 16B chunk within 256B row
    const uint32_t mswz = (uint32_t)((mm ^ (2 * (mrow0 & 7))) * 16);
    const float* mCTA = mask + ((size_t)bh * Sv + (size_t)qt * TQ) * (size_t)Sv;
    const float* msrc0 = mCTA + (size_t)mrow0 * Sv + mm * 4;
    const uint32_t mdst0 = (uint32_t)(mrow0 * 256) + mswz;

    // ---- Q A-fragments straight from gmem ----
    uint32_t qa[4][4];
    #pragma unroll
    for (int kb = 0; kb < 4; ++kb) {
        float2 a0 = *(const float2*)(qlo + kb * 16 + 2 * qd);
        float2 a1 = *(const float2*)(qhi + kb * 16 + 2 * qd);
        float2 a2 = *(const float2*)(qlo + kb * 16 + 8 + 2 * qd);
        float2 a3 = *(const float2*)(qhi + kb * 16 + 8 + 2 * qd);
        qa[kb][0] = f2h2(a0.x, a0.y);
        qa[kb][1] = f2h2(a1.x, a1.y);
        qa[kb][2] = f2h2(a2.x, a2.y);
        qa[kb][3] = f2h2(a3.x, a3.y);
    }

    float o[8][4];
    #pragma unroll
    for (int j = 0; j < 8; ++j) { o[j][0] = o[j][1] = o[j][2] = o[j][3] = 0.0f; }
    // 4 independent normalizer accumulators (short dependency chains)
    float r0a = 0.0f, r0b = 0.0f, r1a = 0.0f, r1b = 0.0f;

    // ---- async issue helpers ----
    auto issue_kv = [&](int kt) {
        const uint32_t KB = sb + OFF_K(kt & 1);
        const uint32_t VB = sb + OFF_V(kt & 1);
        const __half* ks = khb + ((size_t)kt * TK + n0) * Dv + c0 * 8;
        const __half* vs = vhb + ((size_t)kt * TK + n0) * Dv + c0 * 8;
        cpasync16(KB + so0, ks);
        cpasync16(KB + so1, ks + 32 * Dv);
        cpasync16(VB + so0, vs);
        cpasync16(VB + so1, vs + 32 * Dv);
    };
    auto issue_mask = [&](int kt) {
        const uint32_t MB = sb + OFF_M(kt & 1) + mdst0;
        const float* ms = msrc0 + (size_t)kt * TK;
        #pragma unroll
        for (int i = 0; i < 8; ++i)
            cpasync16(MB + (uint32_t)(i * 16 * 256), ms + (size_t)i * 16 * Sv);
    };

    // prologue: tile 0 in flight
    issue_kv(0);
    issue_mask(0);
    CP_COMMIT();

    // x4 ldmatrix lane-address components (validated in R6)
    const int lrow8  = lane & 7;
    const int lkhalf = ((lane >> 3) & 1) * 16;
    const int lrow16 = lane & 15;
    const int grp    = lane >> 4;            // 0/1: second-block selector

    for (int kt = 0; kt < NT; ++kt) {
        __syncthreads();                 // WAR: prev-iter reads of reissued slot done
        if (kt + 1 < NT) { issue_kv(kt + 1); issue_mask(kt + 1); }
        CP_COMMIT();
        CP_WAIT1();                      // tile kt (KV + mask) complete
        __syncthreads();                 // cross-thread visibility

        const uint32_t KBc = sb + OFF_K(kt & 1);
        const uint32_t VBc = sb + OFF_V(kt & 1);
        const uint32_t mb  = sb + OFF_M(kt & 1) + (uint32_t)((R + tq) * 256) + (uint32_t)(qd * 8);

        // ---- GEMM1: S(16x64) = Q @ K^T  (x4 ldsm: two k-chunks per load) ----
        float c[8][4];
        #pragma unroll
        for (int j = 0; j < 8; ++j) { c[j][0] = c[j][1] = c[j][2] = c[j][3] = 0.0f; }
        #pragma unroll
        for (int j = 0; j < 8; ++j) {
            #pragma unroll
            for (int kbp = 0; kbp < 2; ++kbp) {
                uint32_t b0, b1, b2, b3;
                ldsm4(b0, b1, b2, b3,
                      KBc + swz(8 * j + lrow8, (2 * kbp + grp) * 32 + lkhalf));
                mma16816(c[j], qa[2 * kbp],     b0, b1);
                mma16816(c[j], qa[2 * kbp + 1], b2, b3);
            }
        }

        // ---- mask multiply (swizzled smem) + |.| + pack P A-frags ----
        uint32_t pa[4][4];
        #pragma unroll
        for (int j = 0; j < 8; ++j) {
            const uint32_t ma = mb + (uint32_t)((j ^ tq) << 5);
            float2 am = lds64(ma);          // row R+tq,   cols 8j+2qd..+1
            float2 bm = lds64(ma + 2048);   // row R+tq+8, same swizzle
            float p0 = c[j][0] * am.x;
            float p1 = c[j][1] * am.y;
            float p2 = c[j][2] * bm.x;
            float p3 = c[j][3] * bm.y;
            if (j & 1) { r0b += fabsf(p0) + fabsf(p1); r1b += fabsf(p2) + fabsf(p3); }
            else       { r0a += fabsf(p0) + fabsf(p1); r1a += fabsf(p2) + fabsf(p3); }
            const int kb = j >> 1, h = (j & 1) << 1;
            pa[kb][h]     = f2h2(p0, p1);
            pa[kb][h + 1] = f2h2(p2, p3);
        }

        // ---- GEMM2: O(16x64) += P @ V  (x4 trans ldsm: two j-blocks per load) ----
        #pragma unroll
        for (int kb = 0; kb < 4; ++kb) {
            #pragma unroll
            for (int jp = 0; jp < 4; ++jp) {
                uint32_t b0, b1, b2, b3;
                ldsm4t(b0, b1, b2, b3,
                       VBc + swz(kb * 16 + lrow16, (2 * jp + grp) * 16));
                mma16816(o[2 * jp],     pa[kb], b0, b1);
                mma16816(o[2 * jp + 1], pa[kb], b2, b3);
            }
        }
    }

    // ---- normalizer quad-reduction ----
    float rlo = r0a + r0b;
    float rhi = r1a + r1b;
    rlo += __shfl_xor_sync(0xffffffffu, rlo, 1);
    rlo += __shfl_xor_sync(0xffffffffu, rlo, 2);
    rhi += __shfl_xor_sync(0xffffffffu, rhi, 1);
    rhi += __shfl_xor_sync(0xffffffffu, rhi, 2);
    const float il = 1.0f / fmaxf(rlo, 1.0f);
    const float ih = 1.0f / fmaxf(rhi, 1.0f);

    // ---- epilogue ----
    #pragma unroll
    for (int j = 0; j < 8; ++j) {
        float2 lo2, hi2;
        lo2.x = o[j][0] * il;  lo2.y = o[j][1] * il;
        hi2.x = o[j][2] * ih;  hi2.y = o[j][3] * ih;
        *(float2*)(olo + 8 * j + 2 * qd) = lo2;
        *(float2*)(ohi + 8 * j + 2 * qd) = hi2;
    }
}

extern "C" void kernel_launch(void* const* d_in, const int* in_sizes, int n_in,
                              void* d_out, int out_size)
{
    const float* q    = (const float*)d_in[0];
    const float* k    = (const float*)d_in[1];
    const float* v    = (const float*)d_in[2];
    const float* mask = (const float*)d_in[3];
    float* out        = (float*)d_out;

    convert_kv_kernel<<<KVN / 8 / 256, 256>>>(k, v);

    cudaFuncSetAttribute(flashret_fp16_kernel,
                         cudaFuncAttributeMaxDynamicSharedMemorySize, SMEM_TOT);
    dim3 grid(Sv / TQ, Bv * Hv);   // (16, 32) = 512 CTAs
    flashret_fp16_kernel<<<grid, NTH, SMEM_TOT>>>(q, mask, out);
}